// round 6
// baseline (speedup 1.0000x reference)
#include <cuda_runtime.h>

// db2 inverse DWT (synthesis), polyphase form, 2 input cols per thread.
// x: [32, 512, 512, 4] NHWC f32  ->  y: [32, 1024, 1024, 1] f32
// Owned pixels fetched via 256-bit L2::evict_first loads; halo via plain nc.
// Stores default policy (dirty lines buffer in L2, drain lazily).

#define IN_H 512
#define IN_W 512
#define IN_B 32

struct F8 { float4 a, b; };

// 256-bit load, L2 evict-first. p must be 32B-aligned.
__device__ __forceinline__ F8 ldg_ef8(const float4* p) {
    unsigned r0,r1,r2,r3,r4,r5,r6,r7;
    asm volatile("ld.global.nc.L2::evict_first.v8.b32 {%0,%1,%2,%3,%4,%5,%6,%7}, [%8];"
                 : "=r"(r0), "=r"(r1), "=r"(r2), "=r"(r3),
                   "=r"(r4), "=r"(r5), "=r"(r6), "=r"(r7)
                 : "l"(p));
    F8 v;
    v.a = make_float4(__uint_as_float(r0), __uint_as_float(r1),
                      __uint_as_float(r2), __uint_as_float(r3));
    v.b = make_float4(__uint_as_float(r4), __uint_as_float(r5),
                      __uint_as_float(r6), __uint_as_float(r7));
    return v;
}

__device__ __forceinline__ void quad2x2(
    const float4& v00, const float4& v01,
    const float4& v10, const float4& v11,
    const float L[2][2], const float G[2][2],
    float out[2][2])
{
    float a0[2] = { v00.x + v00.y, v10.x + v10.y };
    float a1[2] = { v01.x + v01.y, v11.x + v11.y };
    float z0[2] = { v00.z, v10.z };
    float z1[2] = { v01.z, v11.z };
    float w0[2] = { v00.w, v10.w };
    float w1[2] = { v01.w, v11.w };

    float r_az[2][2], r_w[2][2];
#pragma unroll
    for (int dv = 0; dv < 2; ++dv) {
#pragma unroll
        for (int ah = 0; ah < 2; ++ah) {
            float r = L[ah][0] * a0[dv];
            r = fmaf(L[ah][1], a1[dv], r);
            r = fmaf(G[ah][0], z0[dv], r);
            r = fmaf(G[ah][1], z1[dv], r);
            r_az[dv][ah] = r;
            r_w[dv][ah] = fmaf(G[ah][0], w0[dv], G[ah][1] * w1[dv]);
        }
    }
#pragma unroll
    for (int av = 0; av < 2; ++av) {
#pragma unroll
        for (int ah = 0; ah < 2; ++ah) {
            float r = L[av][0] * r_az[0][ah];
            r = fmaf(L[av][1], r_az[1][ah], r);
            r = fmaf(G[av][0], r_w[0][ah], r);
            r = fmaf(G[av][1], r_w[1][ah], r);
            out[av][ah] = r;
        }
    }
}

__global__ __launch_bounds__(256)
void idwt_db2_kernel(const float4* __restrict__ x, float4* __restrict__ y) {
    const int uu = blockIdx.x * blockDim.x + threadIdx.x;
    const int u  = uu & 255;        // 0..255 (col pair)
    const int s  = uu >> 8;         // 0..511 (input row)
    const int b  = blockIdx.z;      // 0..31

    const float h0 = 0.48296291314469025f;
    const float h1 = 0.83651630373780790f;
    const float h2 = 0.22414386804185735f;
    const float h3 = -0.12940952255092145f;
    const float L[2][2] = { { h2,  h0 }, {  h3,  h1 } };
    const float G[2][2] = { { h1,  h3 }, { -h0, -h2 } };

    const int t0 = 2 * u;
    const int t2 = min(2 * u + 2, IN_W - 1);
    const int s1 = min(s + 1, IN_H - 1);

    const size_t r0 = ((size_t)b * IN_H + s ) * IN_W;
    const size_t r1 = ((size_t)b * IN_H + s1) * IN_W;

    // 2x 32B owned loads + 2x 16B halo loads, all issued up front
    const F8     A  = ldg_ef8(&x[r0 + t0]);
    const F8     B  = ldg_ef8(&x[r1 + t0]);
    const float4 A2 = __ldg(&x[r0 + t2]);
    const float4 B2 = __ldg(&x[r1 + t2]);

    float oA[2][2], oB[2][2];
    quad2x2(A.a, A.b, B.a, B.b, L, G, oA);   // out cols 4u..4u+1
    quad2x2(A.b, A2,  B.b, B2,  L, G, oB);   // out cols 4u+2..4u+3

    const size_t ob = ((size_t)b * 1024 + 2 * s) * 256 + u;
    y[ob]       = make_float4(oA[0][0], oA[0][1], oB[0][0], oB[0][1]);
    y[ob + 256] = make_float4(oA[1][0], oA[1][1], oB[1][0], oB[1][1]);
}

extern "C" void kernel_launch(void* const* d_in, const int* in_sizes, int n_in,
                              void* d_out, int out_size) {
    const float4* x = (const float4*)d_in[0];
    float4* y = (float4*)d_out;
    dim3 block(256, 1, 1);
    dim3 grid((256 * 512) / 256, 1, IN_B);
    idwt_db2_kernel<<<grid, block>>>(x, y);
}